// round 13
// baseline (speedup 1.0000x reference)
#include <cuda_runtime.h>
#include <cuda_bf16.h>

#define ROWS_PER_BLOCK 32
#define TPR   6                  // threads per row; each does 4 items = 2 packed pairs
#define PI_F 3.14159265358979f

typedef unsigned long long u64;

__device__ __forceinline__ float fsqrt_fast(float x){float y;asm("sqrt.approx.f32 %0, %1;":"=f"(y):"f"(x));return y;}
__device__ __forceinline__ float frcp_fast (float x){float y;asm("rcp.approx.f32 %0, %1;":"=f"(y):"f"(x));return y;}

// ---- packed f32x2 helpers (PTX ISA 8.6, sm_100+) ----
__device__ __forceinline__ u64 pk2(float lo, float hi){
    u64 r; asm("mov.b64 %0, {%1, %2};" : "=l"(r)
               : "r"(__float_as_uint(lo)), "r"(__float_as_uint(hi))); return r;
}
__device__ __forceinline__ void upk2(u64 v, float& lo, float& hi){
    unsigned a, b; asm("mov.b64 {%0, %1}, %2;" : "=r"(a), "=r"(b) : "l"(v));
    lo = __uint_as_float(a); hi = __uint_as_float(b);
}
__device__ __forceinline__ u64 mul2_(u64 a, u64 b){u64 d;asm("mul.rn.f32x2 %0, %1, %2;":"=l"(d):"l"(a),"l"(b));return d;}
__device__ __forceinline__ u64 add2_(u64 a, u64 b){u64 d;asm("add.rn.f32x2 %0, %1, %2;":"=l"(d):"l"(a),"l"(b));return d;}
__device__ __forceinline__ u64 fma2_(u64 a, u64 b, u64 c){u64 d;asm("fma.rn.f32x2 %0, %1, %2, %3;":"=l"(d):"l"(a),"l"(b),"l"(c));return d;}
__device__ __forceinline__ u64 bc2(float x){           // broadcast literal -> packed
    unsigned u = __float_as_uint(x);
    return ((u64)u << 32) | u;
}

// Compute two items (a, b) of one row. acos via A&S 4.4.45 (abs err 6.7e-5),
// polynomials evaluated packed; sin(acos x) = sqrt(1-x^2).
__device__ __forceinline__ void pair_compute(
    float2 gc, float dist, u64 PD2, u64 PTWOD,
    float2 gA, float2 gB, float spa, float spb,
    float& lossA, float& lossB)
{
    const u64 NEG1 = bc2(-1.0f), ONE2 = bc2(1.0f);
    const u64 C3 = bc2(-0.0187293f), C2 = bc2(0.0742610f),
              C1 = bc2(-0.2121144f), C0 = bc2(1.5707288f);

    // scale_gt (scalar: MUFU chain)
    const float vxa = gA.x - gc.x, vya = gA.y - gc.y;
    const float vxb = gB.x - gc.x, vyb = gB.y - gc.y;
    const float sga = fsqrt_fast(fmaf(vxa, vxa, vya * vya));
    const float sgb = fsqrt_fast(fmaf(vxb, vxb, vyb * vyb));

    const float minra = fminf(sga, spa), maxra = fmaxf(sga, spa);
    const float minrb = fminf(sgb, spb), maxrb = fmaxf(sgb, spb);

    // packed mid-section
    const u64 pmin  = pk2(minra, minrb);
    const u64 pmax  = pk2(maxra, maxrb);
    const u64 pmin2 = mul2_(pmin, pmin);
    const u64 pmax2 = mul2_(pmax, pmax);
    const u64 pdiff = fma2_(pmin2, NEG1, pmax2);      // maxr2 - minr2  (>= 0)
    const u64 pnmin = fma2_(pdiff, NEG1, PD2);        // d2 - diff
    const u64 pnmax = add2_(PD2, pdiff);              // d2 + diff      (>= 0)

    // combined reciprocal: rinv = 1/(2*d*minr*maxr)
    const u64 pdm  = mul2_(pmin, PTWOD);              // 2*d*minr (also gives md below)
    const u64 pden = mul2_(pdm, pmax);                // 2*d*minr*maxr
    float den_a, den_b, dm_a, dm_b;
    upk2(pden, den_a, den_b);
    upk2(pdm,  dm_a,  dm_b);
    const u64 prinv = pk2(frcp_fast(den_a), frcp_fast(den_b));

    float acmin_a, acmin_b, acmax_a, acmax_b;
    upk2(mul2_(mul2_(pnmin, pmax), prinv), acmin_a, acmin_b);
    upk2(mul2_(mul2_(pnmax, pmin), prinv), acmax_a, acmax_b);
    acmin_a = fminf(fmaxf(acmin_a, -0.99f), 0.99f);
    acmin_b = fminf(fmaxf(acmin_b, -0.99f), 0.99f);
    acmax_a = fminf(acmax_a, 0.99f);   // analytically >= 0 (num,den >= 0)
    acmax_b = fminf(acmax_b, 0.99f);

    const u64 paxm = pk2(fabsf(acmin_a), fabsf(acmin_b));
    const u64 paxx = pk2(acmax_a, acmax_b);

    // acos polynomials, packed (3 fma2 each)
    u64 pm = fma2_(paxm, C3, C2); pm = fma2_(paxm, pm, C1); pm = fma2_(paxm, pm, C0);
    u64 px = fma2_(paxx, C3, C2); px = fma2_(paxx, px, C1); px = fma2_(paxx, px, C0);
    const u64 p1m = fma2_(paxm, NEG1, ONE2);          // 1 - |acmin|
    const u64 p1x = fma2_(paxx, NEG1, ONE2);          // 1 - acmax

    float w_a, w_b, y_a, y_b, pm_a, pm_b, px_a, px_b;
    upk2(p1m, w_a, w_b); upk2(p1x, y_a, y_b);
    upk2(pm, pm_a, pm_b); upk2(px, px_a, px_b);

    float angm_a = fsqrt_fast(w_a) * pm_a; if (acmin_a < 0.0f) angm_a = PI_F - angm_a;
    float angm_b = fsqrt_fast(w_b) * pm_b; if (acmin_b < 0.0f) angm_b = PI_F - angm_b;
    const float angx_a = fsqrt_fast(y_a) * px_a;      // acmax >= 0: no fixup
    const float angx_b = fsqrt_fast(y_b) * px_b;

    // sin(acos(acmin)) = sqrt(1 - acmin^2); |acmin| <= 0.99 so arg >= 0.0199
    const float s1a = fsqrt_fast(fmaf(-acmin_a, acmin_a, 1.0f));
    const float s1b = fsqrt_fast(fmaf(-acmin_b, acmin_b, 1.0f));

    float minr2a, minr2b, maxr2a, maxr2b;
    upk2(pmin2, minr2a, minr2b);
    upk2(pmax2, maxr2a, maxr2b);

    // md = minr*dist = 0.5 * (2*d*minr)
    const float md_a = 0.5f * dm_a, md_b = 0.5f * dm_b;
    const float inter_a = fmaf(angm_a, minr2a, fmaf(angx_a, maxr2a, -(md_a * s1a)));
    const float inter_b = fmaf(angm_b, minr2b, fmaf(angx_b, maxr2b, -(md_b * s1b)));

    // ---- scalar tails (loss = 2 - res/u - u/cs as two FFMA + two rcp) ----
    {
        const float sum = sga + spa;
        const bool contained = fabsf(sga - spa) >= dist;
        const bool disjoint  = dist >= sum;
        const float res = disjoint ? 0.0f : (contained ? PI_F * minr2a : inter_a);
        const float u   = fmaf(PI_F, minr2a + maxr2a, -res);   // area - res > 0 a.s.
        const float cl  = contained ? maxra : 0.5f * (sum + dist);
        const float cs  = PI_F * cl * cl;
        lossA = fmaf(-u, frcp_fast(cs), fmaf(-res, frcp_fast(u), 2.0f));
    }
    {
        const float sum = sgb + spb;
        const bool contained = fabsf(sgb - spb) >= dist;
        const bool disjoint  = dist >= sum;
        const float res = disjoint ? 0.0f : (contained ? PI_F * minr2b : inter_b);
        const float u   = fmaf(PI_F, minr2b + maxr2b, -res);
        const float cl  = contained ? maxrb : 0.5f * (sum + dist);
        const float cs  = PI_F * cl * cl;
        lossB = fmaf(-u, frcp_fast(cs), fmaf(-res, frcp_fast(u), 2.0f));
    }
}

__global__ __launch_bounds__(TPR * ROWS_PER_BLOCK, 6)
void giou_loss_kernel(const float* __restrict__ pred,
                      const float* __restrict__ target,
                      float* __restrict__ out, int N) {
    const int tx  = threadIdx.x;                               // 0..5
    const int row = blockIdx.x * ROWS_PER_BLOCK + threadIdx.y;
    if (row >= N) return;

    const float* __restrict__ t = target + (size_t)row * 50;
    const float* __restrict__ p = pred   + (size_t)row * 26;

    // Headers: default policy (L1 reuse across the 6 lanes of this row)
    const float2 gc = *reinterpret_cast<const float2*>(t);   // gt_cx, gt_cy
    const float2 pc = *reinterpret_cast<const float2*>(p);   // pd_cx, pd_cy

    const float ddx = gc.x - pc.x, ddy = gc.y - pc.y;
    const float dist = fsqrt_fast(fmaf(ddx, ddx, ddy * ddy));
    const float d2   = dist * dist;
    const u64 PD2   = pk2(d2, d2);
    const u64 PTWOD = pk2(2.0f * dist, 2.0f * dist);

    if (tx == 0) {
        __stcs(out + (size_t)N * 24 + row, pc.x);
        __stcs(out + (size_t)N * 25 + row, pc.y);
    }

    // this thread's 4 contiguous items: j = 4*tx + {0,1,2,3} -- streaming loads
    const float2* __restrict__ gxy = reinterpret_cast<const float2*>(t + 2 + 8 * tx);
    const float2 g0 = __ldcs(gxy + 0), g1 = __ldcs(gxy + 1),
                 g2 = __ldcs(gxy + 2), g3 = __ldcs(gxy + 3);
    const float2 spA = __ldcs(reinterpret_cast<const float2*>(p + 2 + 4 * tx));
    const float2 spB = __ldcs(reinterpret_cast<const float2*>(p + 4 + 4 * tx));

    float l0, l1, l2, l3;
    pair_compute(gc, dist, PD2, PTWOD, g0, g1, spA.x, spA.y, l0, l1);
    pair_compute(gc, dist, PD2, PTWOD, g2, g3, spB.x, spB.y, l2, l3);

    // shared output offset: byte addr = 96*row + 16*tx -> 16B-aligned
    const size_t obase = (size_t)row * 24 + 4 * tx;

    // loss: STG.128 evict-first
    __stcs(reinterpret_cast<float4*>(out + obase), make_float4(l0, l1, l2, l3));

    // scale_pd: byte addr = 4*(N*26) + 96*row + 16*tx, all 16B multiples -> STG.128
    __stcs(reinterpret_cast<float4*>(out + (size_t)N * 26 + obase),
           make_float4(spA.x, spA.y, spB.x, spB.y));
}

extern "C" void kernel_launch(void* const* d_in, const int* in_sizes, int n_in,
                              void* d_out, int out_size) {
    const float* pred   = (const float*)d_in[0];
    const float* target = (const float*)d_in[1];
    float* out = (float*)d_out;
    int N = in_sizes[0] / 26;
    int grid = (N + ROWS_PER_BLOCK - 1) / ROWS_PER_BLOCK;
    giou_loss_kernel<<<grid, dim3(TPR, ROWS_PER_BLOCK)>>>(pred, target, out, N);
}

// round 14
// speedup vs baseline: 1.1907x; 1.1907x over previous
#include <cuda_runtime.h>
#include <cuda_bf16.h>

#define ROWS_PER_BLOCK 32
#define TPR   6                  // threads per row; each does 4 items = 2 packed pairs
#define PI_F 3.14159265358979f

typedef unsigned long long u64;

__device__ __forceinline__ float fsqrt_fast(float x){float y;asm("sqrt.approx.f32 %0, %1;":"=f"(y):"f"(x));return y;}
__device__ __forceinline__ float frcp_fast (float x){float y;asm("rcp.approx.f32 %0, %1;":"=f"(y):"f"(x));return y;}

// ---- packed f32x2 helpers (PTX ISA 8.6, sm_100+) ----
__device__ __forceinline__ u64 pk2(float lo, float hi){
    u64 r; asm("mov.b64 %0, {%1, %2};" : "=l"(r)
               : "r"(__float_as_uint(lo)), "r"(__float_as_uint(hi))); return r;
}
__device__ __forceinline__ void upk2(u64 v, float& lo, float& hi){
    unsigned a, b; asm("mov.b64 {%0, %1}, %2;" : "=r"(a), "=r"(b) : "l"(v));
    lo = __uint_as_float(a); hi = __uint_as_float(b);
}
__device__ __forceinline__ u64 mul2_(u64 a, u64 b){u64 d;asm("mul.rn.f32x2 %0, %1, %2;":"=l"(d):"l"(a),"l"(b));return d;}
__device__ __forceinline__ u64 add2_(u64 a, u64 b){u64 d;asm("add.rn.f32x2 %0, %1, %2;":"=l"(d):"l"(a),"l"(b));return d;}
__device__ __forceinline__ u64 fma2_(u64 a, u64 b, u64 c){u64 d;asm("fma.rn.f32x2 %0, %1, %2, %3;":"=l"(d):"l"(a),"l"(b),"l"(c));return d;}
__device__ __forceinline__ u64 bc2(float x){           // broadcast literal -> packed
    unsigned u = __float_as_uint(x);
    return ((u64)u << 32) | u;
}

// Compute two items (a, b) of one row. acos via A&S 4.4.45 (abs err 6.7e-5),
// polynomials evaluated packed; sin(acos x) = sqrt(1-x^2).
__device__ __forceinline__ void pair_compute(
    float2 gc, float dist, u64 PD2, u64 PTWOD,
    float2 gA, float2 gB, float spa, float spb,
    float& lossA, float& lossB)
{
    const u64 NEG1 = bc2(-1.0f), ONE2 = bc2(1.0f);
    const u64 C3 = bc2(-0.0187293f), C2 = bc2(0.0742610f),
              C1 = bc2(-0.2121144f), C0 = bc2(1.5707288f);

    // scale_gt (scalar: MUFU chain)
    const float vxa = gA.x - gc.x, vya = gA.y - gc.y;
    const float vxb = gB.x - gc.x, vyb = gB.y - gc.y;
    const float sga = fsqrt_fast(fmaf(vxa, vxa, vya * vya));
    const float sgb = fsqrt_fast(fmaf(vxb, vxb, vyb * vyb));

    const float minra = fminf(sga, spa), maxra = fmaxf(sga, spa);
    const float minrb = fminf(sgb, spb), maxrb = fmaxf(sgb, spb);

    // packed mid-section
    const u64 pmin  = pk2(minra, minrb);
    const u64 pmax  = pk2(maxra, maxrb);
    const u64 pmin2 = mul2_(pmin, pmin);
    const u64 pmax2 = mul2_(pmax, pmax);
    const u64 pdiff = fma2_(pmin2, NEG1, pmax2);      // maxr2 - minr2  (>= 0)
    const u64 pnmin = fma2_(pdiff, NEG1, PD2);        // d2 - diff
    const u64 pnmax = add2_(PD2, pdiff);              // d2 + diff      (>= 0)

    // combined reciprocal: rinv = 1/(2*d*minr*maxr)
    const u64 pdm  = mul2_(pmin, PTWOD);              // 2*d*minr (also gives md below)
    const u64 pden = mul2_(pdm, pmax);                // 2*d*minr*maxr
    float den_a, den_b, dm_a, dm_b;
    upk2(pden, den_a, den_b);
    upk2(pdm,  dm_a,  dm_b);
    const u64 prinv = pk2(frcp_fast(den_a), frcp_fast(den_b));

    float acmin_a, acmin_b, acmax_a, acmax_b;
    upk2(mul2_(mul2_(pnmin, pmax), prinv), acmin_a, acmin_b);
    upk2(mul2_(mul2_(pnmax, pmin), prinv), acmax_a, acmax_b);
    acmin_a = fminf(fmaxf(acmin_a, -0.99f), 0.99f);
    acmin_b = fminf(fmaxf(acmin_b, -0.99f), 0.99f);
    acmax_a = fminf(acmax_a, 0.99f);   // analytically >= 0 (num,den >= 0)
    acmax_b = fminf(acmax_b, 0.99f);

    const u64 paxm = pk2(fabsf(acmin_a), fabsf(acmin_b));
    const u64 paxx = pk2(acmax_a, acmax_b);

    // acos polynomials, packed (3 fma2 each)
    u64 pm = fma2_(paxm, C3, C2); pm = fma2_(paxm, pm, C1); pm = fma2_(paxm, pm, C0);
    u64 px = fma2_(paxx, C3, C2); px = fma2_(paxx, px, C1); px = fma2_(paxx, px, C0);
    const u64 p1m = fma2_(paxm, NEG1, ONE2);          // 1 - |acmin|
    const u64 p1x = fma2_(paxx, NEG1, ONE2);          // 1 - acmax

    float w_a, w_b, y_a, y_b, pm_a, pm_b, px_a, px_b;
    upk2(p1m, w_a, w_b); upk2(p1x, y_a, y_b);
    upk2(pm, pm_a, pm_b); upk2(px, px_a, px_b);

    float angm_a = fsqrt_fast(w_a) * pm_a; if (acmin_a < 0.0f) angm_a = PI_F - angm_a;
    float angm_b = fsqrt_fast(w_b) * pm_b; if (acmin_b < 0.0f) angm_b = PI_F - angm_b;
    const float angx_a = fsqrt_fast(y_a) * px_a;      // acmax >= 0: no fixup
    const float angx_b = fsqrt_fast(y_b) * px_b;

    // sin(acos(acmin)) = sqrt(1 - acmin^2); |acmin| <= 0.99 so arg >= 0.0199
    const float s1a = fsqrt_fast(fmaf(-acmin_a, acmin_a, 1.0f));
    const float s1b = fsqrt_fast(fmaf(-acmin_b, acmin_b, 1.0f));

    float minr2a, minr2b, maxr2a, maxr2b;
    upk2(pmin2, minr2a, minr2b);
    upk2(pmax2, maxr2a, maxr2b);

    // md = minr*dist = 0.5 * (2*d*minr)
    const float md_a = 0.5f * dm_a, md_b = 0.5f * dm_b;
    const float inter_a = fmaf(angm_a, minr2a, fmaf(angx_a, maxr2a, -(md_a * s1a)));
    const float inter_b = fmaf(angm_b, minr2b, fmaf(angx_b, maxr2b, -(md_b * s1b)));

    // ---- scalar tails (loss = 2 - res/u - u/cs as two FFMA + two rcp) ----
    {
        const float sum = sga + spa;
        const bool contained = fabsf(sga - spa) >= dist;
        const bool disjoint  = dist >= sum;
        const float res = disjoint ? 0.0f : (contained ? PI_F * minr2a : inter_a);
        const float u   = fmaf(PI_F, minr2a + maxr2a, -res);   // area - res > 0 a.s.
        const float cl  = contained ? maxra : 0.5f * (sum + dist);
        const float cs  = PI_F * cl * cl;
        lossA = fmaf(-u, frcp_fast(cs), fmaf(-res, frcp_fast(u), 2.0f));
    }
    {
        const float sum = sgb + spb;
        const bool contained = fabsf(sgb - spb) >= dist;
        const bool disjoint  = dist >= sum;
        const float res = disjoint ? 0.0f : (contained ? PI_F * minr2b : inter_b);
        const float u   = fmaf(PI_F, minr2b + maxr2b, -res);
        const float cl  = contained ? maxrb : 0.5f * (sum + dist);
        const float cs  = PI_F * cl * cl;
        lossB = fmaf(-u, frcp_fast(cs), fmaf(-res, frcp_fast(u), 2.0f));
    }
}

__global__ __launch_bounds__(TPR * ROWS_PER_BLOCK, 6)
void giou_loss_kernel(const float* __restrict__ pred,
                      const float* __restrict__ target,
                      float* __restrict__ out, int N) {
    const int tx  = threadIdx.x;                               // 0..5
    const int row = blockIdx.x * ROWS_PER_BLOCK + threadIdx.y;
    if (row >= N) return;

    const float* __restrict__ t = target + (size_t)row * 50;
    const float* __restrict__ p = pred   + (size_t)row * 26;

    const float2 gc = *reinterpret_cast<const float2*>(t);   // gt_cx, gt_cy
    const float2 pc = *reinterpret_cast<const float2*>(p);   // pd_cx, pd_cy

    const float ddx = gc.x - pc.x, ddy = gc.y - pc.y;
    const float dist = fsqrt_fast(fmaf(ddx, ddx, ddy * ddy));
    const float d2   = dist * dist;
    const u64 PD2   = pk2(d2, d2);
    const u64 PTWOD = pk2(2.0f * dist, 2.0f * dist);

    if (tx == 0) {
        out[(size_t)N * 24 + row] = pc.x;
        out[(size_t)N * 25 + row] = pc.y;
    }

    // this thread's 4 contiguous items: j = 4*tx + {0,1,2,3}
    const float2* __restrict__ gxy = reinterpret_cast<const float2*>(t + 2 + 8 * tx);
    const float2 g0 = gxy[0], g1 = gxy[1], g2 = gxy[2], g3 = gxy[3];
    const float2 spA = *reinterpret_cast<const float2*>(p + 2 + 4 * tx);
    const float2 spB = *reinterpret_cast<const float2*>(p + 4 + 4 * tx);

    float l0, l1, l2, l3;
    pair_compute(gc, dist, PD2, PTWOD, g0, g1, spA.x, spA.y, l0, l1);
    pair_compute(gc, dist, PD2, PTWOD, g2, g3, spB.x, spB.y, l2, l3);

    // shared output offset: byte addr = 96*row + 16*tx -> 16B-aligned
    const size_t obase = (size_t)row * 24 + 4 * tx;

    // loss: STG.128
    *reinterpret_cast<float4*>(out + obase) = make_float4(l0, l1, l2, l3);

    // scale_pd: byte addr = 4*(N*26) + 96*row + 16*tx, all 16B multiples -> STG.128
    *reinterpret_cast<float4*>(out + (size_t)N * 26 + obase) =
        make_float4(spA.x, spA.y, spB.x, spB.y);
}

extern "C" void kernel_launch(void* const* d_in, const int* in_sizes, int n_in,
                              void* d_out, int out_size) {
    const float* pred   = (const float*)d_in[0];
    const float* target = (const float*)d_in[1];
    float* out = (float*)d_out;
    int N = in_sizes[0] / 26;
    int grid = (N + ROWS_PER_BLOCK - 1) / ROWS_PER_BLOCK;
    giou_loss_kernel<<<grid, dim3(TPR, ROWS_PER_BLOCK)>>>(pred, target, out, N);
}